// round 16
// baseline (speedup 1.0000x reference)
#include <cuda_runtime.h>
#include <cuda_fp16.h>
#include <cstdint>
#include <math.h>

// Problem dims
#define T_DIM 1024
#define B_DIM 16
#define H_DIM 1024
#define L_DIM 3
#define M_DIM (T_DIM * B_DIM)   // 16384
#define N_DIM (3 * H_DIM)       // 3072
#define K_DIM H_DIM             // 1024
#define NCH   (B_DIM * H_DIM)   // 16384 scan channels
#define NPAIR (NCH / 2)         // 8192 channel pairs

// GEMM tiling (fp16 operands, fp32 accum) — best-known shape
#define BM 128
#define BN 128
#define BK 64
#define K_ITERS (K_DIM / BK)     // 16
#define WM 64
#define WN 32
#define MT (WM / 16)             // 4
#define NT (WN / 8)              // 4
#define ROWB 144                 // bytes per SMEM row (72 halves, padded)
#define TILE_BYTES (128 * ROWB)
#define STAGE_BYTES (2 * TILE_BYTES)
#define STAGES 3
#define SM_TOTAL (STAGES * STAGE_BYTES)    // 110592
#define CROW 136                 // halves per staged-C smem row (272B, 4g+t banks)

// Scan chunking (best-measured: 16)
#define S_CHUNKS 16
#define CHUNK_T (T_DIM / S_CHUNKS)  // 64

// prep kernel split
#define EMBED_BLOCKS ((M_DIM * H_DIM / 4) / 256)   // 16384
#define TRANS_BLOCKS (96 * 32 * L_DIM)             // 9216

// Scratch (device globals, no runtime alloc)
__device__ __half g_h0[(size_t)M_DIM * H_DIM];
__device__ __half g_h1[(size_t)M_DIM * H_DIM];
__device__ __half g_G [(size_t)M_DIM * N_DIM];
__device__ __half g_Wt[(size_t)L_DIM * N_DIM * K_DIM];
__device__ float  g_P [(size_t)S_CHUNKS * NCH];
__device__ float  g_Q [(size_t)S_CHUNKS * NCH];

// ---------------------------------------------------------------------------
// PTX helpers (sm_80-era only; compute_103 target rejects tcgen05)
// ---------------------------------------------------------------------------
__device__ __forceinline__ uint32_t smem_to_u32(const void* p) {
    uint32_t a;
    asm("{ .reg .u64 t; cvta.to.shared.u64 t, %1; cvt.u32.u64 %0, t; }" : "=r"(a) : "l"(p));
    return a;
}
#define CP_ASYNC16(sa, gp) \
    asm volatile("cp.async.cg.shared.global [%0], [%1], 16;" :: "r"(sa), "l"(gp))
#define CP_COMMIT() asm volatile("cp.async.commit_group;" ::: "memory")
#define CP_WAIT1()  asm volatile("cp.async.wait_group 1;" ::: "memory")
#define CP_WAIT0()  asm volatile("cp.async.wait_group 0;" ::: "memory")

#define LDSM_X4(r0, r1, r2, r3, addr) \
    asm volatile("ldmatrix.sync.aligned.m8n8.x4.shared.b16 {%0,%1,%2,%3}, [%4];" \
                 : "=r"(r0), "=r"(r1), "=r"(r2), "=r"(r3) : "r"(addr))

__device__ __forceinline__ void mma_f16(float& c0, float& c1, float& c2, float& c3,
                                        uint32_t a0, uint32_t a1, uint32_t a2, uint32_t a3,
                                        uint32_t b0, uint32_t b1) {
    asm volatile("mma.sync.aligned.m16n8k16.row.col.f32.f16.f16.f32 "
                 "{%0,%1,%2,%3}, {%4,%5,%6,%7}, {%8,%9}, {%0,%1,%2,%3};"
                 : "+f"(c0), "+f"(c1), "+f"(c2), "+f"(c3)
                 : "r"(a0), "r"(a1), "r"(a2), "r"(a3), "r"(b0), "r"(b1));
}

// ---------------------------------------------------------------------------
// MUFU-based activations (2 MUFU + few FMA each; ~2 ulp, saturation-safe)
// ---------------------------------------------------------------------------
__device__ __forceinline__ float mufu_ex2(float x) {
    float r;
    asm("ex2.approx.f32 %0, %1;" : "=f"(r) : "f"(x));
    return r;
}
__device__ __forceinline__ float mufu_rcp(float x) {
    float r;
    asm("rcp.approx.f32 %0, %1;" : "=f"(r) : "f"(x));
    return r;
}
__device__ __forceinline__ float tanh_fast(float x) {
    float e = mufu_ex2(2.88539008f * x);
    return fmaf(-2.0f, mufu_rcp(e + 1.0f), 1.0f);
}
__device__ __forceinline__ float sigmoid_fast(float x) {
    float e = mufu_ex2(-1.44269504f * x);
    return mufu_rcp(1.0f + e);
}

// ---------------------------------------------------------------------------
// Fused prep: embedding gather (blocks [0, EMBED_BLOCKS)) and
// W transpose + fp16 round (blocks [EMBED_BLOCKS, +TRANS_BLOCKS)).
// ---------------------------------------------------------------------------
__global__ void prep_kernel(const int* __restrict__ x,
                            const float* __restrict__ emb,
                            const float* __restrict__ W,
                            __half* __restrict__ h,
                            __half* __restrict__ Wt)
{
    __shared__ float tile[32][33];
    const int tid = threadIdx.x;

    if (blockIdx.x < EMBED_BLOCKS) {
        int idx = blockIdx.x * 256 + tid;
        int i   = idx * 4;
        int tb  = i >> 10;
        int hh  = i & (H_DIM - 1);
        int tok = x[tb];
        float4 v = *(const float4*)(emb + (size_t)tok * H_DIM + hh);
        __half2 lo = __floats2half2_rn(v.x, v.y);
        __half2 hi = __floats2half2_rn(v.z, v.w);
        uint2 pk = { *(uint32_t*)&lo, *(uint32_t*)&hi };
        *(uint2*)(h + i) = pk;
    } else {
        int bid = blockIdx.x - EMBED_BLOCKS;
        int l   = bid / (96 * 32);
        int rem = bid % (96 * 32);
        int n0  = (rem % 96) * 32;
        int k0  = (rem / 96) * 32;
        int tx  = tid & 31, ty = tid >> 5;   // 32 x 8
        #pragma unroll
        for (int j = 0; j < 32; j += 8) {
            int k = k0 + ty + j, n = n0 + tx;
            tile[ty + j][tx] = W[((size_t)l * K_DIM + k) * N_DIM + n];
        }
        __syncthreads();
        #pragma unroll
        for (int j = 0; j < 32; j += 8) {
            int n = n0 + ty + j, k = k0 + tx;
            Wt[((size_t)l * N_DIM + n) * K_DIM + k] = __float2half_rn(tile[tx][ty + j]);
        }
    }
}

// ---------------------------------------------------------------------------
// FP16 tensor-core GEMM: 128x128 CTA, 8 warps (2x4), ldmatrix, 3-stage
// cp.async pipeline, fragment ping-pong, MUFU epilogue with SMEM-staged
// fully-coalesced stores.
// ---------------------------------------------------------------------------
__global__ __launch_bounds__(256, 2)
void gemm_tc_kernel(const __half* __restrict__ A,
                    const __half* __restrict__ Bt,
                    const float* __restrict__ bias,
                    __half* __restrict__ C)
{
    extern __shared__ char smem[];

    const int tid = threadIdx.x;
    const int wid = tid >> 5;
    const int lid = tid & 31;
    const int g   = lid >> 2;
    const int t   = lid & 3;
    const int bm  = blockIdx.y * BM;
    const int bn  = blockIdx.x * BN;
    const int wm  = (wid >> 2) * WM;
    const int wn  = (wid & 3) * WN;

    const int l_row = tid >> 3;
    const int l_cir = tid & 7;
    const __half* Ag = A  + (size_t)(bm + l_row) * K_DIM + l_cir * 8;
    const __half* Bg = Bt + (size_t)(bn + l_row) * K_DIM + l_cir * 8;
    const uint32_t smem_base = smem_to_u32(smem);
    const uint32_t sAo = smem_base + l_row * ROWB + l_cir * 16;
    const uint32_t sBo = sAo + TILE_BYTES;

    const int r8 = lid & 7;
    const int q  = lid >> 3;
    uint32_t aoff[MT], boff[NT / 2];
    #pragma unroll
    for (int mt = 0; mt < MT; mt++)
        aoff[mt] = (uint32_t)((wm + mt * 16 + r8 + (q & 1) * 8) * ROWB + (q >> 1) * 16);
    #pragma unroll
    for (int p = 0; p < NT / 2; p++)
        boff[p] = (uint32_t)(TILE_BYTES + (wn + p * 16 + r8 + (q >> 1) * 8) * ROWB
                             + (q & 1) * 16);

    float acc[MT][NT][4];
    #pragma unroll
    for (int i = 0; i < MT; i++)
        #pragma unroll
        for (int j = 0; j < NT; j++)
            #pragma unroll
            for (int r = 0; r < 4; r++) acc[i][j][r] = 0.0f;

    #pragma unroll
    for (int p = 0; p < 2; p++) {
        const uint32_t soff = p * STAGE_BYTES;
        const __half* Ak = Ag + p * BK;
        const __half* Bk = Bg + p * BK;
        #pragma unroll
        for (int j = 0; j < 4; j++) {
            CP_ASYNC16(sAo + soff + j * 32 * ROWB, Ak + (size_t)(j * 32) * K_DIM);
            CP_ASYNC16(sBo + soff + j * 32 * ROWB, Bk + (size_t)(j * 32) * K_DIM);
        }
        CP_COMMIT();
    }

    int stg = 0, wst = 2;
    for (int i = 0; i < K_ITERS; i++) {
        if (i + 1 < K_ITERS) CP_WAIT1(); else CP_WAIT0();
        __syncthreads();

        if (i + 2 < K_ITERS) {
            const uint32_t soff = wst * STAGE_BYTES;
            const __half* Ak = Ag + (i + 2) * BK;
            const __half* Bk = Bg + (i + 2) * BK;
            #pragma unroll
            for (int j = 0; j < 4; j++) {
                CP_ASYNC16(sAo + soff + j * 32 * ROWB, Ak + (size_t)(j * 32) * K_DIM);
                CP_ASYNC16(sBo + soff + j * 32 * ROWB, Bk + (size_t)(j * 32) * K_DIM);
            }
            CP_COMMIT();
        }

        const uint32_t sbase = smem_base + stg * STAGE_BYTES;

        uint32_t af[2][MT][4], bf[2][NT][2];
        #pragma unroll
        for (int mt = 0; mt < MT; mt++)
            LDSM_X4(af[0][mt][0], af[0][mt][1], af[0][mt][2], af[0][mt][3],
                    sbase + aoff[mt]);
        #pragma unroll
        for (int p = 0; p < NT / 2; p++)
            LDSM_X4(bf[0][2*p][0], bf[0][2*p][1], bf[0][2*p+1][0], bf[0][2*p+1][1],
                    sbase + boff[p]);

        #pragma unroll
        for (int ks = 0; ks < 4; ks++) {
            const int cur = ks & 1;
            const int nxt = cur ^ 1;
            if (ks < 3) {
                const uint32_t kb = (ks + 1) * 32;
                #pragma unroll
                for (int mt = 0; mt < MT; mt++)
                    LDSM_X4(af[nxt][mt][0], af[nxt][mt][1], af[nxt][mt][2], af[nxt][mt][3],
                            sbase + aoff[mt] + kb);
                #pragma unroll
                for (int p = 0; p < NT / 2; p++)
                    LDSM_X4(bf[nxt][2*p][0], bf[nxt][2*p][1],
                            bf[nxt][2*p+1][0], bf[nxt][2*p+1][1],
                            sbase + boff[p] + kb);
            }
            #pragma unroll
            for (int mt = 0; mt < MT; mt++)
                #pragma unroll
                for (int nt = 0; nt < NT; nt++)
                    mma_f16(acc[mt][nt][0], acc[mt][nt][1],
                            acc[mt][nt][2], acc[mt][nt][3],
                            af[cur][mt][0], af[cur][mt][1],
                            af[cur][mt][2], af[cur][mt][3],
                            bf[cur][nt][0], bf[cur][nt][1]);
        }

        stg = (stg == 2) ? 0 : stg + 1;
        wst = (wst == 2) ? 0 : wst + 1;
    }

    // ---- epilogue: activate into SMEM stage, then fully-coalesced stores
    float bw0[NT], bw1[NT];
    #pragma unroll
    for (int nt = 0; nt < NT; nt++) {
        const int col = bn + wn + nt * 8 + 2 * t;
        bw0[nt] = __ldg(&bias[col]);
        bw1[nt] = __ldg(&bias[col + 1]);
    }
    __syncthreads();                       // mainloop done; smem reusable
    __half* cs = (__half*)smem;            // staged C tile: [128][CROW]
    #pragma unroll
    for (int mt = 0; mt < MT; mt++) {
        const int r0 = wm + mt * 16 + g;   // tile-local row
        #pragma unroll
        for (int nt = 0; nt < NT; nt++) {
            const int cl  = wn + nt * 8 + 2 * t;      // tile-local col
            const int gcl = bn + cl;                  // global col (gate select)
            float2 v0, v1;
            if (gcl < H_DIM) {
                v0.x = tanh_fast(acc[mt][nt][0] + bw0[nt]);
                v0.y = tanh_fast(acc[mt][nt][1] + bw1[nt]);
                v1.x = tanh_fast(acc[mt][nt][2] + bw0[nt]);
                v1.y = tanh_fast(acc[mt][nt][3] + bw1[nt]);
            } else {
                v0.x = sigmoid_fast(acc[mt][nt][0] + bw0[nt]);
                v0.y = sigmoid_fast(acc[mt][nt][1] + bw1[nt]);
                v1.x = sigmoid_fast(acc[mt][nt][2] + bw0[nt]);
                v1.y = sigmoid_fast(acc[mt][nt][3] + bw1[nt]);
            }
            *(__half2*)&cs[(r0    ) * CROW + cl] = __floats2half2_rn(v0.x, v0.y);
            *(__half2*)&cs[(r0 + 8) * CROW + cl] = __floats2half2_rn(v1.x, v1.y);
        }
    }
    __syncthreads();
    // flat stores: 128 rows x 16 uint4; warp covers 512B in 256B runs
    #pragma unroll
    for (int u = tid; u < 128 * 16; u += 256) {
        const int row = u >> 4;
        const int c16 = u & 15;
        uint4 v = *(uint4*)(cs + row * CROW + c16 * 8);
        *(uint4*)&C[(size_t)(bm + row) * N_DIM + bn + c16 * 8] = v;
    }
}

// ---------------------------------------------------------------------------
// Chunked-parallel forget-mult scan over fp16 gates, half2 channel pairs.
// Two-pass; S_CHUNKS=16. pass1 skips the last chunk (map has no consumer).
// ---------------------------------------------------------------------------
__global__ void scan_pass1(const __half* __restrict__ G,
                           float* __restrict__ P, float* __restrict__ Q)
{
    const int id = blockIdx.x * blockDim.x + threadIdx.x;
    const int j2 = id & (NPAIR - 1);
    const int s  = id >> 13;
    const int b  = j2 >> 9;
    const int hh = (j2 & 511) * 2;
    const __half* gz = G + ((size_t)(s * CHUNK_T) * B_DIM + b) * N_DIM + hh;

    float2 c = {0.0f, 0.0f}, p = {1.0f, 1.0f};
    #pragma unroll 8
    for (int t = 0; t < CHUNK_T; t++) {
        const __half* ptr = gz + (size_t)t * (B_DIM * N_DIM);
        float2 z = __half22float2(*(const __half2*)(ptr));
        float2 f = __half22float2(*(const __half2*)(ptr + H_DIM));
        c.x = fmaf(f.x, z.x - c.x, c.x);
        c.y = fmaf(f.y, z.y - c.y, c.y);
        p.x *= (1.0f - f.x);
        p.y *= (1.0f - f.y);
    }
    *(float2*)&P[(size_t)s * NCH + 2 * j2] = p;
    *(float2*)&Q[(size_t)s * NCH + 2 * j2] = c;
}

__global__ void scan_pass2(const __half* __restrict__ G,
                           const float* __restrict__ P, const float* __restrict__ Q,
                           float* __restrict__ outf, __half* __restrict__ outh,
                           int Tout, int write_half)
{
    const int id = blockIdx.x * blockDim.x + threadIdx.x;
    const int j2 = id & (NPAIR - 1);
    const int s  = id >> 13;
    const int b  = j2 >> 9;
    const int hh = (j2 & 511) * 2;

    float2 c = {0.0f, 0.0f};
    for (int ss = 0; ss < s; ss++) {
        float2 p2 = *(const float2*)&P[(size_t)ss * NCH + 2 * j2];
        float2 q2 = *(const float2*)&Q[(size_t)ss * NCH + 2 * j2];
        c.x = fmaf(p2.x, c.x, q2.x);
        c.y = fmaf(p2.y, c.y, q2.y);
    }

    const __half* gz = G + ((size_t)(s * CHUNK_T) * B_DIM + b) * N_DIM + hh;
    const size_t obase = ((size_t)(s * CHUNK_T) * B_DIM + b) * H_DIM + hh;
    const int tmax = Tout - s * CHUNK_T;
    #pragma unroll 8
    for (int t = 0; t < CHUNK_T; t++) {
        const __half* ptr = gz + (size_t)t * (B_DIM * N_DIM);
        float2 z = __half22float2(*(const __half2*)(ptr));
        float2 f = __half22float2(*(const __half2*)(ptr + H_DIM));
        float2 o = __half22float2(*(const __half2*)(ptr + 2 * H_DIM));
        c.x = fmaf(f.x, z.x - c.x, c.x);
        c.y = fmaf(f.y, z.y - c.y, c.y);
        if (t < tmax) {
            const size_t oi = obase + (size_t)t * (B_DIM * H_DIM);
            if (write_half)
                *(__half2*)&outh[oi] = __floats2half2_rn(o.x * c.x, o.y * c.y);
            else
                *(float2*)&outf[oi] = make_float2(o.x * c.x, o.y * c.y);
        }
    }
}

// ---------------------------------------------------------------------------
extern "C" void kernel_launch(void* const* d_in, const int* in_sizes, int n_in,
                              void* d_out, int out_size)
{
    const int*   x    = (const int*)  d_in[0];
    const float* emb  = (const float*)d_in[1];
    const float* W    = (const float*)d_in[2];
    const float* bias = (const float*)d_in[3];
    float* out = (float*)d_out;

    __half *h0, *h1, *Wt, *G;
    float *P, *Q;
    cudaGetSymbolAddress((void**)&h0, g_h0);
    cudaGetSymbolAddress((void**)&h1, g_h1);
    cudaGetSymbolAddress((void**)&G,  g_G);
    cudaGetSymbolAddress((void**)&Wt, g_Wt);
    cudaGetSymbolAddress((void**)&P,  g_P);
    cudaGetSymbolAddress((void**)&Q,  g_Q);

    static bool attr_set = false;
    if (!attr_set) {
        cudaFuncSetAttribute(gemm_tc_kernel,
                             cudaFuncAttributeMaxDynamicSharedMemorySize, SM_TOTAL);
        attr_set = true;
    }

    prep_kernel<<<EMBED_BLOCKS + TRANS_BLOCKS, 256>>>(x, emb, W, h0, Wt);

    dim3 ggrid(N_DIM / BN, M_DIM / BM);                      // (24, 128)
    const int sgrid1 = ((S_CHUNKS - 1) * NPAIR) / 256;       // 480 blocks
    const int sgrid2 = (S_CHUNKS * NPAIR) / 256;             // 512 blocks

    gemm_tc_kernel<<<ggrid, 256, SM_TOTAL>>>(h0, Wt + 0 * (size_t)N_DIM * K_DIM,
                                             bias + 0 * N_DIM, G);
    scan_pass1<<<sgrid1, 256>>>(G, P, Q);
    scan_pass2<<<sgrid2, 256>>>(G, P, Q, nullptr, h1, T_DIM, 1);

    gemm_tc_kernel<<<ggrid, 256, SM_TOTAL>>>(h1, Wt + 1 * (size_t)N_DIM * K_DIM,
                                             bias + 1 * N_DIM, G);
    scan_pass1<<<sgrid1, 256>>>(G, P, Q);
    scan_pass2<<<sgrid2, 256>>>(G, P, Q, nullptr, h0, T_DIM, 1);

    gemm_tc_kernel<<<ggrid, 256, SM_TOTAL>>>(h0, Wt + 2 * (size_t)N_DIM * K_DIM,
                                             bias + 2 * N_DIM, G);
    scan_pass1<<<sgrid1, 256>>>(G, P, Q);
    scan_pass2<<<sgrid2, 256>>>(G, P, Q, out, nullptr, T_DIM - 1, 0);
}

// round 17
// speedup vs baseline: 1.0081x; 1.0081x over previous
#include <cuda_runtime.h>
#include <cuda_fp16.h>
#include <cstdint>
#include <math.h>

// Problem dims
#define T_DIM 1024
#define B_DIM 16
#define H_DIM 1024
#define L_DIM 3
#define M_DIM (T_DIM * B_DIM)   // 16384
#define N_DIM (3 * H_DIM)       // 3072
#define K_DIM H_DIM             // 1024
#define NCH   (B_DIM * H_DIM)   // 16384 scan channels
#define NPAIR (NCH / 2)         // 8192 channel pairs

// GEMM tiling (fp16 operands, fp32 accum) — best-known shape
#define BM 128
#define BN 128
#define BK 64
#define K_ITERS (K_DIM / BK)     // 16
#define WM 64
#define WN 32
#define MT (WM / 16)             // 4
#define NT (WN / 8)              // 4
#define ROWB 144                 // bytes per SMEM row (72 halves, padded)
#define TILE_BYTES (128 * ROWB)
#define STAGE_BYTES (2 * TILE_BYTES)
#define STAGES 3
#define SM_TOTAL (STAGES * STAGE_BYTES)    // 110592

// Scan chunking (best-measured: 16)
#define S_CHUNKS 16
#define CHUNK_T (T_DIM / S_CHUNKS)  // 64

// prep kernel split
#define EMBED_BLOCKS ((M_DIM * H_DIM / 4) / 256)   // 16384
#define TRANS_BLOCKS (96 * 32 * L_DIM)             // 9216

// Scratch (device globals, no runtime alloc)
__device__ __half g_h0[(size_t)M_DIM * H_DIM];
__device__ __half g_h1[(size_t)M_DIM * H_DIM];
__device__ __half g_G [(size_t)M_DIM * N_DIM];
__device__ __half g_Wt[(size_t)L_DIM * N_DIM * K_DIM];
__device__ float  g_P [(size_t)S_CHUNKS * NCH];
__device__ float  g_Q [(size_t)S_CHUNKS * NCH];

// ---------------------------------------------------------------------------
// PTX helpers (sm_80-era only; compute_103 target rejects tcgen05)
// ---------------------------------------------------------------------------
__device__ __forceinline__ uint32_t smem_to_u32(const void* p) {
    uint32_t a;
    asm("{ .reg .u64 t; cvta.to.shared.u64 t, %1; cvt.u32.u64 %0, t; }" : "=r"(a) : "l"(p));
    return a;
}
#define CP_ASYNC16(sa, gp) \
    asm volatile("cp.async.cg.shared.global [%0], [%1], 16;" :: "r"(sa), "l"(gp))
#define CP_COMMIT() asm volatile("cp.async.commit_group;" ::: "memory")
#define CP_WAIT1()  asm volatile("cp.async.wait_group 1;" ::: "memory")
#define CP_WAIT0()  asm volatile("cp.async.wait_group 0;" ::: "memory")

#define LDSM_X4(r0, r1, r2, r3, addr) \
    asm volatile("ldmatrix.sync.aligned.m8n8.x4.shared.b16 {%0,%1,%2,%3}, [%4];" \
                 : "=r"(r0), "=r"(r1), "=r"(r2), "=r"(r3) : "r"(addr))

__device__ __forceinline__ void mma_f16(float& c0, float& c1, float& c2, float& c3,
                                        uint32_t a0, uint32_t a1, uint32_t a2, uint32_t a3,
                                        uint32_t b0, uint32_t b1) {
    asm volatile("mma.sync.aligned.m16n8k16.row.col.f32.f16.f16.f32 "
                 "{%0,%1,%2,%3}, {%4,%5,%6,%7}, {%8,%9}, {%0,%1,%2,%3};"
                 : "+f"(c0), "+f"(c1), "+f"(c2), "+f"(c3)
                 : "r"(a0), "r"(a1), "r"(a2), "r"(a3), "r"(b0), "r"(b1));
}

// ---------------------------------------------------------------------------
// MUFU-based activations (2 MUFU + few FMA each; ~2 ulp, saturation-safe)
// ---------------------------------------------------------------------------
__device__ __forceinline__ float mufu_ex2(float x) {
    float r;
    asm("ex2.approx.f32 %0, %1;" : "=f"(r) : "f"(x));
    return r;
}
__device__ __forceinline__ float mufu_rcp(float x) {
    float r;
    asm("rcp.approx.f32 %0, %1;" : "=f"(r) : "f"(x));
    return r;
}
__device__ __forceinline__ float tanh_fast(float x) {
    float e = mufu_ex2(2.88539008f * x);
    return fmaf(-2.0f, mufu_rcp(e + 1.0f), 1.0f);
}
__device__ __forceinline__ float sigmoid_fast(float x) {
    float e = mufu_ex2(-1.44269504f * x);
    return mufu_rcp(1.0f + e);
}

// ---------------------------------------------------------------------------
// Fused prep: embedding gather (blocks [0, EMBED_BLOCKS)) and
// W transpose + fp16 round (blocks [EMBED_BLOCKS, +TRANS_BLOCKS)).
// ---------------------------------------------------------------------------
__global__ void prep_kernel(const int* __restrict__ x,
                            const float* __restrict__ emb,
                            const float* __restrict__ W,
                            __half* __restrict__ h,
                            __half* __restrict__ Wt)
{
    __shared__ float tile[32][33];
    const int tid = threadIdx.x;

    if (blockIdx.x < EMBED_BLOCKS) {
        int idx = blockIdx.x * 256 + tid;
        int i   = idx * 4;
        int tb  = i >> 10;
        int hh  = i & (H_DIM - 1);
        int tok = x[tb];
        float4 v = *(const float4*)(emb + (size_t)tok * H_DIM + hh);
        __half2 lo = __floats2half2_rn(v.x, v.y);
        __half2 hi = __floats2half2_rn(v.z, v.w);
        uint2 pk = { *(uint32_t*)&lo, *(uint32_t*)&hi };
        *(uint2*)(h + i) = pk;
    } else {
        int bid = blockIdx.x - EMBED_BLOCKS;
        int l   = bid / (96 * 32);
        int rem = bid % (96 * 32);
        int n0  = (rem % 96) * 32;
        int k0  = (rem / 96) * 32;
        int tx  = tid & 31, ty = tid >> 5;   // 32 x 8
        #pragma unroll
        for (int j = 0; j < 32; j += 8) {
            int k = k0 + ty + j, n = n0 + tx;
            tile[ty + j][tx] = W[((size_t)l * K_DIM + k) * N_DIM + n];
        }
        __syncthreads();
        #pragma unroll
        for (int j = 0; j < 32; j += 8) {
            int n = n0 + ty + j, k = k0 + tx;
            Wt[((size_t)l * N_DIM + n) * K_DIM + k] = __float2half_rn(tile[tx][ty + j]);
        }
    }
}

// ---------------------------------------------------------------------------
// FP16 tensor-core GEMM (best-known): 128x128 CTA, 8 warps (2x4), ldmatrix,
// 3-stage cp.async pipeline, fragment ping-pong, MUFU epilogue with direct
// half2 stores (R15 form — staging through SMEM measured slower).
// ---------------------------------------------------------------------------
__global__ __launch_bounds__(256, 2)
void gemm_tc_kernel(const __half* __restrict__ A,
                    const __half* __restrict__ Bt,
                    const float* __restrict__ bias,
                    __half* __restrict__ C)
{
    extern __shared__ char smem[];

    const int tid = threadIdx.x;
    const int wid = tid >> 5;
    const int lid = tid & 31;
    const int g   = lid >> 2;
    const int t   = lid & 3;
    const int bm  = blockIdx.y * BM;
    const int bn  = blockIdx.x * BN;
    const int wm  = (wid >> 2) * WM;
    const int wn  = (wid & 3) * WN;

    const int l_row = tid >> 3;
    const int l_cir = tid & 7;
    const __half* Ag = A  + (size_t)(bm + l_row) * K_DIM + l_cir * 8;
    const __half* Bg = Bt + (size_t)(bn + l_row) * K_DIM + l_cir * 8;
    const uint32_t smem_base = smem_to_u32(smem);
    const uint32_t sAo = smem_base + l_row * ROWB + l_cir * 16;
    const uint32_t sBo = sAo + TILE_BYTES;

    const int r8 = lid & 7;
    const int q  = lid >> 3;
    uint32_t aoff[MT], boff[NT / 2];
    #pragma unroll
    for (int mt = 0; mt < MT; mt++)
        aoff[mt] = (uint32_t)((wm + mt * 16 + r8 + (q & 1) * 8) * ROWB + (q >> 1) * 16);
    #pragma unroll
    for (int p = 0; p < NT / 2; p++)
        boff[p] = (uint32_t)(TILE_BYTES + (wn + p * 16 + r8 + (q >> 1) * 8) * ROWB
                             + (q & 1) * 16);

    float acc[MT][NT][4];
    #pragma unroll
    for (int i = 0; i < MT; i++)
        #pragma unroll
        for (int j = 0; j < NT; j++)
            #pragma unroll
            for (int r = 0; r < 4; r++) acc[i][j][r] = 0.0f;

    #pragma unroll
    for (int p = 0; p < 2; p++) {
        const uint32_t soff = p * STAGE_BYTES;
        const __half* Ak = Ag + p * BK;
        const __half* Bk = Bg + p * BK;
        #pragma unroll
        for (int j = 0; j < 4; j++) {
            CP_ASYNC16(sAo + soff + j * 32 * ROWB, Ak + (size_t)(j * 32) * K_DIM);
            CP_ASYNC16(sBo + soff + j * 32 * ROWB, Bk + (size_t)(j * 32) * K_DIM);
        }
        CP_COMMIT();
    }

    int stg = 0, wst = 2;
    for (int i = 0; i < K_ITERS; i++) {
        if (i + 1 < K_ITERS) CP_WAIT1(); else CP_WAIT0();
        __syncthreads();

        if (i + 2 < K_ITERS) {
            const uint32_t soff = wst * STAGE_BYTES;
            const __half* Ak = Ag + (i + 2) * BK;
            const __half* Bk = Bg + (i + 2) * BK;
            #pragma unroll
            for (int j = 0; j < 4; j++) {
                CP_ASYNC16(sAo + soff + j * 32 * ROWB, Ak + (size_t)(j * 32) * K_DIM);
                CP_ASYNC16(sBo + soff + j * 32 * ROWB, Bk + (size_t)(j * 32) * K_DIM);
            }
            CP_COMMIT();
        }

        const uint32_t sbase = smem_base + stg * STAGE_BYTES;

        uint32_t af[2][MT][4], bf[2][NT][2];
        #pragma unroll
        for (int mt = 0; mt < MT; mt++)
            LDSM_X4(af[0][mt][0], af[0][mt][1], af[0][mt][2], af[0][mt][3],
                    sbase + aoff[mt]);
        #pragma unroll
        for (int p = 0; p < NT / 2; p++)
            LDSM_X4(bf[0][2*p][0], bf[0][2*p][1], bf[0][2*p+1][0], bf[0][2*p+1][1],
                    sbase + boff[p]);

        #pragma unroll
        for (int ks = 0; ks < 4; ks++) {
            const int cur = ks & 1;
            const int nxt = cur ^ 1;
            if (ks < 3) {
                const uint32_t kb = (ks + 1) * 32;
                #pragma unroll
                for (int mt = 0; mt < MT; mt++)
                    LDSM_X4(af[nxt][mt][0], af[nxt][mt][1], af[nxt][mt][2], af[nxt][mt][3],
                            sbase + aoff[mt] + kb);
                #pragma unroll
                for (int p = 0; p < NT / 2; p++)
                    LDSM_X4(bf[nxt][2*p][0], bf[nxt][2*p][1],
                            bf[nxt][2*p+1][0], bf[nxt][2*p+1][1],
                            sbase + boff[p] + kb);
            }
            #pragma unroll
            for (int mt = 0; mt < MT; mt++)
                #pragma unroll
                for (int nt = 0; nt < NT; nt++)
                    mma_f16(acc[mt][nt][0], acc[mt][nt][1],
                            acc[mt][nt][2], acc[mt][nt][3],
                            af[cur][mt][0], af[cur][mt][1],
                            af[cur][mt][2], af[cur][mt][3],
                            bf[cur][nt][0], bf[cur][nt][1]);
        }

        stg = (stg == 2) ? 0 : stg + 1;
        wst = (wst == 2) ? 0 : wst + 1;
    }

    // epilogue: hoisted bias, MUFU activations, direct half2 stores
    float bw0[NT], bw1[NT];
    #pragma unroll
    for (int nt = 0; nt < NT; nt++) {
        const int col = bn + wn + nt * 8 + 2 * t;
        bw0[nt] = __ldg(&bias[col]);
        bw1[nt] = __ldg(&bias[col + 1]);
    }
    #pragma unroll
    for (int mt = 0; mt < MT; mt++) {
        const int row0 = bm + wm + mt * 16 + g;
        #pragma unroll
        for (int nt = 0; nt < NT; nt++) {
            const int col = bn + wn + nt * 8 + 2 * t;
            float2 v0, v1;
            if (col < H_DIM) {
                v0.x = tanh_fast(acc[mt][nt][0] + bw0[nt]);
                v0.y = tanh_fast(acc[mt][nt][1] + bw1[nt]);
                v1.x = tanh_fast(acc[mt][nt][2] + bw0[nt]);
                v1.y = tanh_fast(acc[mt][nt][3] + bw1[nt]);
            } else {
                v0.x = sigmoid_fast(acc[mt][nt][0] + bw0[nt]);
                v0.y = sigmoid_fast(acc[mt][nt][1] + bw1[nt]);
                v1.x = sigmoid_fast(acc[mt][nt][2] + bw0[nt]);
                v1.y = sigmoid_fast(acc[mt][nt][3] + bw1[nt]);
            }
            *(__half2*)&C[(size_t)row0 * N_DIM + col]       = __floats2half2_rn(v0.x, v0.y);
            *(__half2*)&C[(size_t)(row0 + 8) * N_DIM + col] = __floats2half2_rn(v1.x, v1.y);
        }
    }
}

// ---------------------------------------------------------------------------
// Chunked-parallel forget-mult scan over fp16 gates, half2 channel pairs.
// Two-pass; S_CHUNKS=16. pass1 skips the last chunk (map has no consumer).
// ---------------------------------------------------------------------------
__global__ void scan_pass1(const __half* __restrict__ G,
                           float* __restrict__ P, float* __restrict__ Q)
{
    const int id = blockIdx.x * blockDim.x + threadIdx.x;
    const int j2 = id & (NPAIR - 1);
    const int s  = id >> 13;
    const int b  = j2 >> 9;
    const int hh = (j2 & 511) * 2;
    const __half* gz = G + ((size_t)(s * CHUNK_T) * B_DIM + b) * N_DIM + hh;

    float2 c = {0.0f, 0.0f}, p = {1.0f, 1.0f};
    #pragma unroll 8
    for (int t = 0; t < CHUNK_T; t++) {
        const __half* ptr = gz + (size_t)t * (B_DIM * N_DIM);
        float2 z = __half22float2(*(const __half2*)(ptr));
        float2 f = __half22float2(*(const __half2*)(ptr + H_DIM));
        c.x = fmaf(f.x, z.x - c.x, c.x);
        c.y = fmaf(f.y, z.y - c.y, c.y);
        p.x *= (1.0f - f.x);
        p.y *= (1.0f - f.y);
    }
    *(float2*)&P[(size_t)s * NCH + 2 * j2] = p;
    *(float2*)&Q[(size_t)s * NCH + 2 * j2] = c;
}

__global__ void scan_pass2(const __half* __restrict__ G,
                           const float* __restrict__ P, const float* __restrict__ Q,
                           float* __restrict__ outf, __half* __restrict__ outh,
                           int Tout, int write_half)
{
    const int id = blockIdx.x * blockDim.x + threadIdx.x;
    const int j2 = id & (NPAIR - 1);
    const int s  = id >> 13;
    const int b  = j2 >> 9;
    const int hh = (j2 & 511) * 2;

    float2 c = {0.0f, 0.0f};
    for (int ss = 0; ss < s; ss++) {
        float2 p2 = *(const float2*)&P[(size_t)ss * NCH + 2 * j2];
        float2 q2 = *(const float2*)&Q[(size_t)ss * NCH + 2 * j2];
        c.x = fmaf(p2.x, c.x, q2.x);
        c.y = fmaf(p2.y, c.y, q2.y);
    }

    const __half* gz = G + ((size_t)(s * CHUNK_T) * B_DIM + b) * N_DIM + hh;
    const size_t obase = ((size_t)(s * CHUNK_T) * B_DIM + b) * H_DIM + hh;
    const int tmax = Tout - s * CHUNK_T;
    #pragma unroll 8
    for (int t = 0; t < CHUNK_T; t++) {
        const __half* ptr = gz + (size_t)t * (B_DIM * N_DIM);
        float2 z = __half22float2(*(const __half2*)(ptr));
        float2 f = __half22float2(*(const __half2*)(ptr + H_DIM));
        float2 o = __half22float2(*(const __half2*)(ptr + 2 * H_DIM));
        c.x = fmaf(f.x, z.x - c.x, c.x);
        c.y = fmaf(f.y, z.y - c.y, c.y);
        if (t < tmax) {
            const size_t oi = obase + (size_t)t * (B_DIM * H_DIM);
            if (write_half)
                *(__half2*)&outh[oi] = __floats2half2_rn(o.x * c.x, o.y * c.y);
            else
                *(float2*)&outf[oi] = make_float2(o.x * c.x, o.y * c.y);
        }
    }
}

// ---------------------------------------------------------------------------
extern "C" void kernel_launch(void* const* d_in, const int* in_sizes, int n_in,
                              void* d_out, int out_size)
{
    const int*   x    = (const int*)  d_in[0];
    const float* emb  = (const float*)d_in[1];
    const float* W    = (const float*)d_in[2];
    const float* bias = (const float*)d_in[3];
    float* out = (float*)d_out;

    __half *h0, *h1, *Wt, *G;
    float *P, *Q;
    cudaGetSymbolAddress((void**)&h0, g_h0);
    cudaGetSymbolAddress((void**)&h1, g_h1);
    cudaGetSymbolAddress((void**)&G,  g_G);
    cudaGetSymbolAddress((void**)&Wt, g_Wt);
    cudaGetSymbolAddress((void**)&P,  g_P);
    cudaGetSymbolAddress((void**)&Q,  g_Q);

    static bool attr_set = false;
    if (!attr_set) {
        cudaFuncSetAttribute(gemm_tc_kernel,
                             cudaFuncAttributeMaxDynamicSharedMemorySize, SM_TOTAL);
        attr_set = true;
    }

    prep_kernel<<<EMBED_BLOCKS + TRANS_BLOCKS, 256>>>(x, emb, W, h0, Wt);

    dim3 ggrid(N_DIM / BN, M_DIM / BM);                      // (24, 128)
    const int sgrid1 = ((S_CHUNKS - 1) * NPAIR) / 256;       // 480 blocks
    const int sgrid2 = (S_CHUNKS * NPAIR) / 256;             // 512 blocks

    gemm_tc_kernel<<<ggrid, 256, SM_TOTAL>>>(h0, Wt + 0 * (size_t)N_DIM * K_DIM,
                                             bias + 0 * N_DIM, G);
    scan_pass1<<<sgrid1, 256>>>(G, P, Q);
    scan_pass2<<<sgrid2, 256>>>(G, P, Q, nullptr, h1, T_DIM, 1);

    gemm_tc_kernel<<<ggrid, 256, SM_TOTAL>>>(h1, Wt + 1 * (size_t)N_DIM * K_DIM,
                                             bias + 1 * N_DIM, G);
    scan_pass1<<<sgrid1, 256>>>(G, P, Q);
    scan_pass2<<<sgrid2, 256>>>(G, P, Q, nullptr, h0, T_DIM, 1);

    gemm_tc_kernel<<<ggrid, 256, SM_TOTAL>>>(h0, Wt + 2 * (size_t)N_DIM * K_DIM,
                                             bias + 2 * N_DIM, G);
    scan_pass1<<<sgrid1, 256>>>(G, P, Q);
    scan_pass2<<<sgrid2, 256>>>(G, P, Q, out, nullptr, T_DIM - 1, 0);
}